// round 2
// baseline (speedup 1.0000x reference)
#include <cuda_runtime.h>
#include <cuda_bf16.h>
#include <cfloat>

// InferenceVectorQuantizer: N=500000 rows of D=64 fp32, codebook K=512 x 64 fp32.
// out = [quantized (N*D fp32) | indices (N, stored as fp32)]
//
// argmin_k ||x-e_k||^2 == argmax_k (x . e_k - 0.5*||e_k||^2)  (||x||^2 dropped).
// Codebook + half-norms live in SMEM (130 KB). One row per thread; inner loop
// is 32 packed dual-FMAs (fma.rn.f32x2, sm_100+) per code with a packed-add
// horizontal reduce. Exact fp32 math -> argmin matches reference.

#define VQ_D 64
#define VQ_K 512
#define VQ_THREADS 512

#if defined(__CUDA_ARCH__) && (__CUDA_ARCH__ >= 1000)
#define VQ_HAS_F32X2 1
#else
#define VQ_HAS_F32X2 0
#endif

__device__ __forceinline__ unsigned long long vq_fma2(
    unsigned long long a, unsigned long long b, unsigned long long c) {
#if VQ_HAS_F32X2
    unsigned long long d;
    asm("fma.rn.f32x2 %0, %1, %2, %3;" : "=l"(d) : "l"(a), "l"(b), "l"(c));
    return d;
#else
    float2 af = *reinterpret_cast<float2*>(&a);
    float2 bf = *reinterpret_cast<float2*>(&b);
    float2 cf = *reinterpret_cast<float2*>(&c);
    cf.x = fmaf(af.x, bf.x, cf.x);
    cf.y = fmaf(af.y, bf.y, cf.y);
    unsigned long long d;
    *reinterpret_cast<float2*>(&d) = cf;
    return d;
#endif
}

__device__ __forceinline__ unsigned long long vq_add2(
    unsigned long long a, unsigned long long b) {
#if VQ_HAS_F32X2
    unsigned long long d;
    asm("add.rn.f32x2 %0, %1, %2;" : "=l"(d) : "l"(a), "l"(b));
    return d;
#else
    float2 af = *reinterpret_cast<float2*>(&a);
    float2 bf = *reinterpret_cast<float2*>(&b);
    af.x += bf.x; af.y += bf.y;
    unsigned long long d;
    *reinterpret_cast<float2*>(&d) = af;
    return d;
#endif
}

__device__ __forceinline__ float vq_hsum2(unsigned long long v) {
    float lo, hi;
    asm("mov.b64 {%0, %1}, %2;" : "=f"(lo), "=f"(hi) : "l"(v));
    return lo + hi;
}

extern __shared__ float smem_dyn[];

__global__ __launch_bounds__(VQ_THREADS, 1)
void vq_kernel(const float* __restrict__ x,
               const float* __restrict__ emb,
               float* __restrict__ out_q,
               float* __restrict__ out_idx,
               int N, int write_idx) {
    float* s_emb = smem_dyn;                 // [K*D] = 32768 floats (128 KB)
    float* s_h   = smem_dyn + VQ_K * VQ_D;   // [K] half squared norms (2 KB)

    const int tid = threadIdx.x;

    // ---- cooperative load of codebook into SMEM (coalesced float4) ----
    {
        const float4* g4 = reinterpret_cast<const float4*>(emb);
        float4* s4 = reinterpret_cast<float4*>(s_emb);
        const int total4 = VQ_K * VQ_D / 4;  // 8192
        #pragma unroll
        for (int i = tid; i < total4; i += VQ_THREADS)
            s4[i] = g4[i];
    }
    __syncthreads();

    // ---- half squared norms: one code row per thread ----
    if (tid < VQ_K) {
        const float4* row = reinterpret_cast<const float4*>(s_emb + tid * VQ_D);
        float s = 0.0f;
        #pragma unroll
        for (int j = 0; j < VQ_D / 4; ++j) {
            float4 v = row[j];
            s += v.x * v.x + v.y * v.y + v.z * v.z + v.w * v.w;
        }
        s_h[tid] = 0.5f * s;
    }
    __syncthreads();

    const int n = blockIdx.x * VQ_THREADS + tid;
    if (n >= N) return;

    // ---- my x row in registers: 16 x ulonglong2 = 64 floats ----
    ulonglong2 xr[VQ_D / 4];
    {
        const ulonglong2* xrow = reinterpret_cast<const ulonglong2*>(x + (size_t)n * VQ_D);
        #pragma unroll
        for (int j = 0; j < VQ_D / 4; ++j) xr[j] = xrow[j];
    }

    const ulonglong2* e2 = reinterpret_cast<const ulonglong2*>(s_emb);

    float best = -FLT_MAX;
    int bi = 0;

    #pragma unroll 2
    for (int k = 0; k < VQ_K; ++k) {
        const ulonglong2* er = e2 + k * (VQ_D / 4);
        unsigned long long c0 = 0ull, c1 = 0ull, c2 = 0ull, c3 = 0ull;
        #pragma unroll
        for (int j = 0; j < VQ_D / 4; j += 2) {
            ulonglong2 ea = er[j];
            ulonglong2 eb = er[j + 1];
            c0 = vq_fma2(xr[j].x,     ea.x, c0);
            c1 = vq_fma2(xr[j].y,     ea.y, c1);
            c2 = vq_fma2(xr[j + 1].x, eb.x, c2);
            c3 = vq_fma2(xr[j + 1].y, eb.y, c3);
        }
        // packed horizontal reduce: 3 packed adds + 1 unpack-add
        c0 = vq_add2(c0, c1);
        c2 = vq_add2(c2, c3);
        c0 = vq_add2(c0, c2);
        float score = vq_hsum2(c0) - s_h[k];
        if (score > best) { best = score; bi = k; }
    }

    // ---- gather winning code row from SMEM, write output ----
    {
        float4* oq = reinterpret_cast<float4*>(out_q + (size_t)n * VQ_D);
        const float4* er = reinterpret_cast<const float4*>(s_emb + bi * VQ_D);
        #pragma unroll
        for (int j = 0; j < VQ_D / 4; ++j) oq[j] = er[j];
    }
    if (write_idx) out_idx[n] = (float)bi;
}

extern "C" void kernel_launch(void* const* d_in, const int* in_sizes, int n_in,
                              void* d_out, int out_size) {
    const float* x   = (const float*)d_in[0];   // [N, 64] fp32
    const float* emb = (const float*)d_in[1];   // [512, 64] fp32
    float* out = (float*)d_out;

    const int N = in_sizes[0] / VQ_D;
    const int write_idx = (out_size >= N * (VQ_D + 1)) ? 1 : 0;

    const int smem_bytes = (VQ_K * VQ_D + VQ_K) * (int)sizeof(float);  // 133120
    cudaFuncSetAttribute(vq_kernel, cudaFuncAttributeMaxDynamicSharedMemorySize, smem_bytes);

    const int grid = (N + VQ_THREADS - 1) / VQ_THREADS;
    vq_kernel<<<grid, VQ_THREADS, smem_bytes>>>(
        x, emb, out, out + (size_t)N * VQ_D, N, write_idx);
}

// round 4
// speedup vs baseline: 1.1934x; 1.1934x over previous
#include <cuda_runtime.h>
#include <cuda_bf16.h>
#include <cfloat>

// InferenceVectorQuantizer: N=500000 rows of D=64 fp32, codebook K=512 x 64 fp32.
// out = [quantized (N*D fp32) | indices (N, stored as fp32)]
//
// argmin_k ||x-e_k||^2 == argmax_k (x . e_k - 0.5*||e_k||^2)  (||x||^2 dropped).
// R2 ncu: L1/shared-bound (90%) from re-fetching codebook per row.
// This round: register-tile 2 rows per thread -> each codebook LDS feeds 2
// rows, balancing LDS wavefronts against the FMA pipe. Exact fp32 math.

#define VQ_D 64
#define VQ_K 512
#define VQ_THREADS 256
#define VQ_ROWS_PER_BLOCK (VQ_THREADS * 2)

#if defined(__CUDA_ARCH__) && (__CUDA_ARCH__ >= 1000)
#define VQ_HAS_F32X2 1
#else
#define VQ_HAS_F32X2 0
#endif

__device__ __forceinline__ unsigned long long vq_fma2(
    unsigned long long a, unsigned long long b, unsigned long long c) {
#if VQ_HAS_F32X2
    unsigned long long d;
    asm("fma.rn.f32x2 %0, %1, %2, %3;" : "=l"(d) : "l"(a), "l"(b), "l"(c));
    return d;
#else
    float2 af = *reinterpret_cast<float2*>(&a);
    float2 bf = *reinterpret_cast<float2*>(&b);
    float2 cf = *reinterpret_cast<float2*>(&c);
    cf.x = fmaf(af.x, bf.x, cf.x);
    cf.y = fmaf(af.y, bf.y, cf.y);
    unsigned long long d;
    *reinterpret_cast<float2*>(&d) = cf;
    return d;
#endif
}

__device__ __forceinline__ unsigned long long vq_add2(
    unsigned long long a, unsigned long long b) {
#if VQ_HAS_F32X2
    unsigned long long d;
    asm("add.rn.f32x2 %0, %1, %2;" : "=l"(d) : "l"(a), "l"(b));
    return d;
#else
    float2 af = *reinterpret_cast<float2*>(&a);
    float2 bf = *reinterpret_cast<float2*>(&b);
    af.x += bf.x; af.y += bf.y;
    unsigned long long d;
    *reinterpret_cast<float2*>(&d) = af;
    return d;
#endif
}

__device__ __forceinline__ float vq_hsum2(unsigned long long v) {
    float lo, hi;
    asm("mov.b64 {%0, %1}, %2;" : "=f"(lo), "=f"(hi) : "l"(v));
    return lo + hi;
}

extern __shared__ float smem_dyn[];

__global__ __launch_bounds__(VQ_THREADS, 1)
void vq_kernel(const float* __restrict__ x,
               const float* __restrict__ emb,
               float* __restrict__ out_q,
               float* __restrict__ out_idx,
               int N, int write_idx) {
    float* s_emb = smem_dyn;                 // [K*D] = 32768 floats (128 KB)
    float* s_h   = smem_dyn + VQ_K * VQ_D;   // [K] half squared norms (2 KB)

    const int tid = threadIdx.x;

    // ---- cooperative load of codebook into SMEM (coalesced float4) ----
    {
        const float4* g4 = reinterpret_cast<const float4*>(emb);
        float4* s4 = reinterpret_cast<float4*>(s_emb);
        const int total4 = VQ_K * VQ_D / 4;  // 8192
        #pragma unroll
        for (int i = tid; i < total4; i += VQ_THREADS)
            s4[i] = g4[i];
    }
    __syncthreads();

    // ---- half squared norms: two code rows per thread ----
    #pragma unroll
    for (int kk = tid; kk < VQ_K; kk += VQ_THREADS) {
        const float4* row = reinterpret_cast<const float4*>(s_emb + kk * VQ_D);
        float s = 0.0f;
        #pragma unroll
        for (int j = 0; j < VQ_D / 4; ++j) {
            float4 v = row[j];
            s += v.x * v.x + v.y * v.y + v.z * v.z + v.w * v.w;
        }
        s_h[kk] = 0.5f * s;
    }
    __syncthreads();

    const int n0 = blockIdx.x * VQ_ROWS_PER_BLOCK + tid;
    const int n1 = n0 + VQ_THREADS;
    const bool v0 = (n0 < N);
    const bool v1 = (n1 < N);
    if (!v0) return;

    // ---- two x rows in registers (each 16 x ulonglong2 = 64 floats) ----
    ulonglong2 x0[VQ_D / 4];
    ulonglong2 x1[VQ_D / 4];
    {
        const ulonglong2* r0 = reinterpret_cast<const ulonglong2*>(x + (size_t)n0 * VQ_D);
        #pragma unroll
        for (int j = 0; j < VQ_D / 4; ++j) x0[j] = r0[j];
    }
    if (v1) {
        const ulonglong2* r1 = reinterpret_cast<const ulonglong2*>(x + (size_t)n1 * VQ_D);
        #pragma unroll
        for (int j = 0; j < VQ_D / 4; ++j) x1[j] = r1[j];
    } else {
        #pragma unroll
        for (int j = 0; j < VQ_D / 4; ++j) { x1[j].x = 0ull; x1[j].y = 0ull; }
    }

    const ulonglong2* e2 = reinterpret_cast<const ulonglong2*>(s_emb);

    float bestA = -FLT_MAX, bestB = -FLT_MAX;
    int biA = 0, biB = 0;

    #pragma unroll 2
    for (int k = 0; k < VQ_K; ++k) {
        const ulonglong2* er = e2 + k * (VQ_D / 4);
        unsigned long long a0 = 0ull, a1 = 0ull, a2 = 0ull, a3 = 0ull;
        unsigned long long b0 = 0ull, b1 = 0ull, b2 = 0ull, b3 = 0ull;
        #pragma unroll
        for (int j = 0; j < VQ_D / 4; j += 2) {
            ulonglong2 ea = er[j];
            ulonglong2 eb = er[j + 1];
            a0 = vq_fma2(x0[j].x,     ea.x, a0);
            b0 = vq_fma2(x1[j].x,     ea.x, b0);
            a1 = vq_fma2(x0[j].y,     ea.y, a1);
            b1 = vq_fma2(x1[j].y,     ea.y, b1);
            a2 = vq_fma2(x0[j + 1].x, eb.x, a2);
            b2 = vq_fma2(x1[j + 1].x, eb.x, b2);
            a3 = vq_fma2(x0[j + 1].y, eb.y, a3);
            b3 = vq_fma2(x1[j + 1].y, eb.y, b3);
        }
        const float h = s_h[k];
        a0 = vq_add2(a0, a1); a2 = vq_add2(a2, a3); a0 = vq_add2(a0, a2);
        b0 = vq_add2(b0, b1); b2 = vq_add2(b2, b3); b0 = vq_add2(b0, b2);
        float sA = vq_hsum2(a0) - h;
        float sB = vq_hsum2(b0) - h;
        if (sA > bestA) { bestA = sA; biA = k; }
        if (sB > bestB) { bestB = sB; biB = k; }
    }

    // ---- gather winning code rows from SMEM, write outputs ----
    {
        float4* oq = reinterpret_cast<float4*>(out_q + (size_t)n0 * VQ_D);
        const float4* er = reinterpret_cast<const float4*>(s_emb + biA * VQ_D);
        #pragma unroll
        for (int j = 0; j < VQ_D / 4; ++j) oq[j] = er[j];
        if (write_idx) out_idx[n0] = (float)biA;
    }
    if (v1) {
        float4* oq = reinterpret_cast<float4*>(out_q + (size_t)n1 * VQ_D);
        const float4* er = reinterpret_cast<const float4*>(s_emb + biB * VQ_D);
        #pragma unroll
        for (int j = 0; j < VQ_D / 4; ++j) oq[j] = er[j];
        if (write_idx) out_idx[n1] = (float)biB;
    }
}

extern "C" void kernel_launch(void* const* d_in, const int* in_sizes, int n_in,
                              void* d_out, int out_size) {
    const float* x   = (const float*)d_in[0];   // [N, 64] fp32
    const float* emb = (const float*)d_in[1];   // [512, 64] fp32
    float* out = (float*)d_out;

    const int N = in_sizes[0] / VQ_D;
    const int write_idx = (out_size >= N * (VQ_D + 1)) ? 1 : 0;

    const int smem_bytes = (VQ_K * VQ_D + VQ_K) * (int)sizeof(float);  // 133120
    cudaFuncSetAttribute(vq_kernel, cudaFuncAttributeMaxDynamicSharedMemorySize, smem_bytes);

    const int grid = (N + VQ_ROWS_PER_BLOCK - 1) / VQ_ROWS_PER_BLOCK;
    vq_kernel<<<grid, VQ_THREADS, smem_bytes>>>(
        x, emb, out, out + (size_t)N * VQ_D, N, write_idx);
}

// round 7
// speedup vs baseline: 2.4842x; 2.0817x over previous
#include <cuda_runtime.h>
#include <cuda_fp16.h>
#include <cfloat>
#include <cstdint>

// InferenceVectorQuantizer via legacy tensor cores (mma.sync, sm_80+ path —
// the harness targets baseline sm_100, so no tcgen05).
// scores = X @ E^T with fp16 hi/lo 4-way split (hh+hl+lh+ll, fp32 accum)
// -> fp32-level accuracy. Fused per-row argmax of (score - 0.5*||e||^2),
// exact fp32 gather of winning codebook row.
// out = [quantized (N*64 fp32) | indices (N as fp32)]

#define VQ_D 64
#define VQ_K 512
#define THREADS 512
#define WARPS (THREADS / 32)
#define ROWS_PER_CTA (WARPS * 16)      // 256

// smem: B_hi[512*128B] | B_lo[512*128B] | h[512 floats]
#define SM_BH 0
#define SM_BL (VQ_K * 128)             // 65536
#define SM_H  (2 * VQ_K * 128)        // 131072
#define SM_TOTAL (SM_H + VQ_K * 4)    // 133120

static __device__ __forceinline__ uint32_t smem_u32(const void* p) {
    uint32_t a;
    asm("{ .reg .u64 t; cvta.to.shared.u64 t, %1; cvt.u32.u64 %0, t; }"
        : "=r"(a) : "l"(p));
    return a;
}

// split float2 -> (hi half2, lo half2) packed as u32 (low half = .x)
static __device__ __forceinline__ void cvt_split(float2 v, uint32_t& hi, uint32_t& lo) {
    __half h0 = __float2half_rn(v.x);
    __half h1 = __float2half_rn(v.y);
    __half l0 = __float2half_rn(v.x - __half2float(h0));
    __half l1 = __float2half_rn(v.y - __half2float(h1));
    __half2 H = __halves2half2(h0, h1);
    __half2 L = __halves2half2(l0, l1);
    hi = *reinterpret_cast<uint32_t*>(&H);
    lo = *reinterpret_cast<uint32_t*>(&L);
}

#define LDSM_X4(r0, r1, r2, r3, a) \
    asm volatile("ldmatrix.sync.aligned.m8n8.x4.shared.b16 {%0,%1,%2,%3}, [%4];" \
                 : "=r"(r0), "=r"(r1), "=r"(r2), "=r"(r3) : "r"(a))

#define MMA16816(c0, c1, c2, c3, a0, a1, a2, a3, b0, b1) \
    asm volatile("mma.sync.aligned.m16n8k16.row.col.f32.f16.f16.f32 " \
                 "{%0,%1,%2,%3}, {%4,%5,%6,%7}, {%8,%9}, {%0,%1,%2,%3};" \
                 : "+f"(c0), "+f"(c1), "+f"(c2), "+f"(c3) \
                 : "r"(a0), "r"(a1), "r"(a2), "r"(a3), "r"(b0), "r"(b1))

extern __shared__ char smem[];

__global__ __launch_bounds__(THREADS, 1)
void vq_mma_kernel(const float* __restrict__ x,
                   const float* __restrict__ emb,
                   float* __restrict__ out_q,
                   float* __restrict__ out_idx,
                   int N, int write_idx) {
    const int tid = threadIdx.x;

    // ---- prologue: codebook -> fp16 hi/lo swizzled smem ----
    // element (code n, half-col k): byte off = n*128 + 2k, swizzle ^= (n&7)<<4
    {
        const float2* e2 = reinterpret_cast<const float2*>(emb);
        #pragma unroll 4
        for (int i = tid; i < (VQ_K * VQ_D) / 2; i += THREADS) {
            int n = i >> 5;          // 32 float2 per code row
            int kp = i & 31;
            float2 v = e2[i];
            uint32_t hi, lo;
            cvt_split(v, hi, lo);
            uint32_t off = (uint32_t)(n * 128 + kp * 4) ^ (uint32_t)((n & 7) << 4);
            *(uint32_t*)(smem + SM_BH + off) = hi;
            *(uint32_t*)(smem + SM_BL + off) = lo;
        }
        // half squared norms
        for (int k = tid; k < VQ_K; k += THREADS) {
            const float4* r = reinterpret_cast<const float4*>(emb + k * VQ_D);
            float s = 0.f;
            #pragma unroll
            for (int j = 0; j < VQ_D / 4; ++j) {
                float4 v = __ldg(r + j);
                s += v.x * v.x + v.y * v.y + v.z * v.z + v.w * v.w;
            }
            ((float*)(smem + SM_H))[k] = 0.5f * s;
        }
    }
    __syncthreads();

    const int wid = tid >> 5;
    const int lane = tid & 31;
    const int qd = lane >> 2;     // 0..7 (row group)
    const int tq = lane & 3;      // 0..3 (col pair)

    const int row0 = blockIdx.x * ROWS_PER_CTA + wid * 16 + qd;
    const int row1 = row0 + 8;
    const bool v0 = (row0 < N);
    const bool v1 = (row1 < N);

    // ---- A fragments straight from gmem (fragment layout of m16n8k16) ----
    // a0=(row0,k), a1=(row1,k), a2=(row0,k+8), a3=(row1,k+8); k = c*16 + tq*2
    uint32_t ah[16], al[16];
    {
        const float2 z = make_float2(0.f, 0.f);
        const float* xr0 = x + (size_t)row0 * VQ_D;
        const float* xr1 = x + (size_t)row1 * VQ_D;
        #pragma unroll
        for (int c = 0; c < 4; ++c) {
            int kb = c * 16 + tq * 2;
            float2 v00 = v0 ? *(const float2*)(xr0 + kb)     : z;
            float2 v10 = v1 ? *(const float2*)(xr1 + kb)     : z;
            float2 v01 = v0 ? *(const float2*)(xr0 + kb + 8) : z;
            float2 v11 = v1 ? *(const float2*)(xr1 + kb + 8) : z;
            cvt_split(v00, ah[4 * c + 0], al[4 * c + 0]);
            cvt_split(v10, ah[4 * c + 1], al[4 * c + 1]);
            cvt_split(v01, ah[4 * c + 2], al[4 * c + 2]);
            cvt_split(v11, ah[4 * c + 3], al[4 * c + 3]);
        }
    }

    // ---- per-lane ldmatrix addresses (swizzled) ----
    const uint32_t sb = smem_u32(smem);
    const int r8 = lane & 7;          // code row within 8-chunk
    const int tsel = lane >> 3;       // which 8x8 tile (k-bytes 0/16/32/48)
    const uint32_t pre0 = (uint32_t)((r8 * 128 + tsel * 16) ^ (r8 << 4));
    const uint32_t pre1 = (uint32_t)((r8 * 128 + 64 + tsel * 16) ^ (r8 << 4));
    const uint32_t bh0a = sb + SM_BH + pre0;
    const uint32_t bh1a = sb + SM_BH + pre1;
    const uint32_t bl0a = sb + SM_BL + pre0;
    const uint32_t bl1a = sb + SM_BL + pre1;
    const float* hs = (const float*)(smem + SM_H);

    float best0 = -FLT_MAX, best1 = -FLT_MAX;
    int bi0 = 0, bi1 = 0;

    // ---- main loop: 64 chunks of 8 codes ----
    #pragma unroll 2
    for (int ch = 0; ch < VQ_K / 8; ++ch) {
        const uint32_t off = (uint32_t)ch * 1024;   // 8 codes * 128B
        uint32_t bh[8], bl[8];
        LDSM_X4(bh[0], bh[1], bh[2], bh[3], bh0a + off);
        LDSM_X4(bh[4], bh[5], bh[6], bh[7], bh1a + off);
        LDSM_X4(bl[0], bl[1], bl[2], bl[3], bl0a + off);
        LDSM_X4(bl[4], bl[5], bl[6], bl[7], bl1a + off);

        float c0 = 0.f, c1 = 0.f, c2 = 0.f, c3 = 0.f;   // hh + hl
        float d0 = 0.f, d1 = 0.f, d2 = 0.f, d3 = 0.f;   // lh + ll
        #pragma unroll
        for (int c = 0; c < 4; ++c) {
            MMA16816(c0, c1, c2, c3, ah[4*c], ah[4*c+1], ah[4*c+2], ah[4*c+3], bh[2*c], bh[2*c+1]);
            MMA16816(d0, d1, d2, d3, al[4*c], al[4*c+1], al[4*c+2], al[4*c+3], bh[2*c], bh[2*c+1]);
        }
        #pragma unroll
        for (int c = 0; c < 4; ++c) {
            MMA16816(c0, c1, c2, c3, ah[4*c], ah[4*c+1], ah[4*c+2], ah[4*c+3], bl[2*c], bl[2*c+1]);
            MMA16816(d0, d1, d2, d3, al[4*c], al[4*c+1], al[4*c+2], al[4*c+3], bl[2*c], bl[2*c+1]);
        }

        const float2 hh = *(const float2*)(hs + ch * 8 + tq * 2);
        const float s0 = (c0 + d0) - hh.x;
        const float s1 = (c1 + d1) - hh.y;
        const float s2 = (c2 + d2) - hh.x;
        const float s3 = (c3 + d3) - hh.y;
        const int col0 = ch * 8 + tq * 2;
        if (s0 > best0) { best0 = s0; bi0 = col0; }
        if (s1 > best0) { best0 = s1; bi0 = col0 + 1; }
        if (s2 > best1) { best1 = s2; bi1 = col0; }
        if (s3 > best1) { best1 = s3; bi1 = col0 + 1; }
    }

    // ---- quad reduce (lanes tq=0..3 share rows) ----
    #pragma unroll
    for (int m = 1; m <= 2; m <<= 1) {
        float ob = __shfl_xor_sync(0xffffffffu, best0, m);
        int   oi = __shfl_xor_sync(0xffffffffu, bi0,  m);
        if (ob > best0 || (ob == best0 && oi < bi0)) { best0 = ob; bi0 = oi; }
        ob = __shfl_xor_sync(0xffffffffu, best1, m);
        oi = __shfl_xor_sync(0xffffffffu, bi1,  m);
        if (ob > best1 || (ob == best1 && oi < bi1)) { best1 = ob; bi1 = oi; }
    }

    // ---- gather winning rows (exact fp32 from gmem/L2), coalesced write ----
    if (v0) {
        const float4* er = (const float4*)(emb + (size_t)bi0 * VQ_D);
        float4* o = (float4*)(out_q + (size_t)row0 * VQ_D);
        const int j0 = tq * 4;
        #pragma unroll
        for (int j = 0; j < 4; ++j) o[j0 + j] = __ldg(er + j0 + j);
        if (write_idx && tq == 0) out_idx[row0] = (float)bi0;
    }
    if (v1) {
        const float4* er = (const float4*)(emb + (size_t)bi1 * VQ_D);
        float4* o = (float4*)(out_q + (size_t)row1 * VQ_D);
        const int j0 = tq * 4;
        #pragma unroll
        for (int j = 0; j < 4; ++j) o[j0 + j] = __ldg(er + j0 + j);
        if (write_idx && tq == 0) out_idx[row1] = (float)bi1;
    }
}

extern "C" void kernel_launch(void* const* d_in, const int* in_sizes, int n_in,
                              void* d_out, int out_size) {
    const float* x   = (const float*)d_in[0];   // [N, 64] fp32
    const float* emb = (const float*)d_in[1];   // [512, 64] fp32
    float* out = (float*)d_out;

    const int N = in_sizes[0] / VQ_D;
    const int write_idx = (out_size >= N * (VQ_D + 1)) ? 1 : 0;

    cudaFuncSetAttribute(vq_mma_kernel, cudaFuncAttributeMaxDynamicSharedMemorySize, SM_TOTAL);

    const int grid = (N + ROWS_PER_CTA - 1) / ROWS_PER_CTA;   // 1954
    vq_mma_kernel<<<grid, THREADS, SM_TOTAL>>>(
        x, emb, out, out + (size_t)N * VQ_D, N, write_idx);
}